// round 6
// baseline (speedup 1.0000x reference)
#include <cuda_runtime.h>
#include <math.h>

#define NN   50000
#define EE   800000
#define CC   5000
#define DD   128
#define OUTF 40
#define CAP  64          // per-node in-edge bin capacity (max deg ~38)
#define RS   64          // padded feature row stride (floats) -> 256B aligned
#define RS4  16          // row stride in float4

#define FILLB 782        // fill blocks (200192 threads for 200000 edge-quads)
#define PROJB 196        // proj blocks (50176 threads for 50000 rows)
#define FUSEDB (FILLB + PROJB)   // 978

// ---- scratch (device globals; no allocation allowed) ----
__device__ int   g_cnt[NN];            // in-degree counts (also bin cursors)
__device__ int   g_srcbuf[NN * CAP];   // binned in-edge source lists
__device__ float g_xp[NN * RS];        // x[v] @ W^T (UNscaled), padded rows
__device__ float g_h1s[NN * RS];       // dinv[v] * h1[v], padded rows
__device__ float g_ycn[CC * OUTF];     // per-cluster log-softmax'd logits

// ---- f32x2 packed helpers (Blackwell FFMA2) ----
__device__ __forceinline__ unsigned long long pk2(float lo, float hi) {
    unsigned long long r;
    asm("mov.b64 %0, {%1, %2};" : "=l"(r) : "f"(lo), "f"(hi));
    return r;
}
__device__ __forceinline__ unsigned long long fma2(unsigned long long a,
                                                   unsigned long long b,
                                                   unsigned long long c) {
    unsigned long long d;
    asm("fma.rn.f32x2 %0, %1, %2, %3;" : "=l"(d) : "l"(a), "l"(b), "l"(c));
    return d;
}
__device__ __forceinline__ void upk2(unsigned long long v, float& a, float& b) {
    asm("mov.b64 {%0, %1}, %2;" : "=f"(a), "=f"(b) : "l"(v));
}

// ---------------------------------------------------------------------------
// Fused kernel: fill (edge binning, atomic) runs CONCURRENTLY with proj
// (dense x@W^T). No data dependency: proj no longer folds dinv.
// Role split: blockIdx.x % 5 == 0 -> proj (196 blocks), else fill (782).
__global__ void __launch_bounds__(256) fused_fill_proj_kernel(
        const int* __restrict__ ei,
        const float* __restrict__ x,
        const float* __restrict__ W) {
    __shared__ ulonglong2 Ws2[OUTF / 2][DD / 2];   // 20KB (reserved by all blocks)

    if (blockIdx.x % 5 != 0) {
        // ---------------- fill role ----------------
        int fb = blockIdx.x - blockIdx.x / 5 - 1;          // 0..FILLB-1
        int e4 = fb * blockDim.x + threadIdx.x;
        if (e4 >= EE / 4) return;
        int4 s = __ldg(((const int4*)ei) + e4);
        int4 d = __ldg(((const int4*)(ei + EE)) + e4);
        int p0 = atomicAdd(&g_cnt[d.x], 1);
        if (p0 < CAP) g_srcbuf[d.x * CAP + p0] = s.x;
        int p1 = atomicAdd(&g_cnt[d.y], 1);
        if (p1 < CAP) g_srcbuf[d.y * CAP + p1] = s.y;
        int p2 = atomicAdd(&g_cnt[d.z], 1);
        if (p2 < CAP) g_srcbuf[d.z * CAP + p2] = s.z;
        int p3 = atomicAdd(&g_cnt[d.w], 1);
        if (p3 < CAP) g_srcbuf[d.w * CAP + p3] = s.w;
        return;
    }

    // ---------------- proj role ----------------
    int pb = blockIdx.x / 5;                               // 0..PROJB-1
    for (int t = threadIdx.x; t < (OUTF / 2) * (DD / 2); t += blockDim.x) {
        int o2 = t / (DD / 2);
        int d2 = t % (DD / 2);
        int d  = 2 * d2;
        float w00 = W[(2 * o2)     * DD + d    ];
        float w10 = W[(2 * o2 + 1) * DD + d    ];
        float w01 = W[(2 * o2)     * DD + d + 1];
        float w11 = W[(2 * o2 + 1) * DD + d + 1];
        Ws2[o2][d2] = make_ulonglong2(pk2(w00, w10), pk2(w01, w11));
    }
    __syncthreads();

    int row = pb * blockDim.x + threadIdx.x;
    if (row >= NN) return;

    unsigned long long acc[OUTF / 2];
    #pragma unroll
    for (int o2 = 0; o2 < OUTF / 2; o2++) acc[o2] = 0ull;

    const float4* xr4 = (const float4*)(x + (size_t)row * DD);
    #pragma unroll 4
    for (int d4 = 0; d4 < DD / 4; d4++) {
        float4 xv = __ldg(&xr4[d4]);
        int d2 = d4 * 2;
        unsigned long long a0 = pk2(xv.x, xv.x);
        unsigned long long a1 = pk2(xv.y, xv.y);
        unsigned long long a2 = pk2(xv.z, xv.z);
        unsigned long long a3 = pk2(xv.w, xv.w);
        #pragma unroll
        for (int o2 = 0; o2 < OUTF / 2; o2++) {
            ulonglong2 w = Ws2[o2][d2];
            acc[o2] = fma2(a0, w.x, acc[o2]);
            acc[o2] = fma2(a1, w.y, acc[o2]);
        }
        #pragma unroll
        for (int o2 = 0; o2 < OUTF / 2; o2++) {
            ulonglong2 w = Ws2[o2][d2 + 1];
            acc[o2] = fma2(a2, w.x, acc[o2]);
            acc[o2] = fma2(a3, w.y, acc[o2]);
        }
    }

    float2* op2 = (float2*)(g_xp + (size_t)row * RS);
    #pragma unroll
    for (int o2 = 0; o2 < OUTF / 2; o2++) {
        float f0, f1;
        upk2(acc[o2], f0, f1);
        op2[o2] = make_float2(f0, f1);
    }
}

// ---------------------------------------------------------------------------
// hop 1: 3 nodes per warp (three 10-lane groups; lanes 30,31 idle).
// h1s[v] = dinv_v^2 * ( dinv_v*xp[v] + sum_in dinv_s*xp[s] ), dinv on the fly.
__global__ void hop1_kernel() {
    int gwarp = (blockIdx.x * blockDim.x + threadIdx.x) >> 5;
    int lane  = threadIdx.x & 31;
    int g = lane / 10;            // group 0..2 (lanes 30-31: g==3, idle)
    int c = lane - g * 10;        // float4 chunk 0..9
    int v = gwarp * 3 + g;
    bool act = (g < 3) && (v < NN);

    const float4* xp4 = (const float4*)g_xp;
    float4 acc = make_float4(0.f, 0.f, 0.f, 0.f);
    float dv = 0.f;
    int deg = 0;
    const int* sb = g_srcbuf;     // safe base for inactive lanes
    if (act) {
        int cv = g_cnt[v];
        deg = min(cv, CAP);
        dv = rsqrtf((float)(cv + 1));
        float4 self = __ldg(&xp4[(size_t)v * RS4 + c]);
        acc = make_float4(dv * self.x, dv * self.y, dv * self.z, dv * self.w);
        sb = g_srcbuf + v * CAP;
    }
    int maxdeg = deg;
    #pragma unroll
    for (int off = 16; off > 0; off >>= 1)
        maxdeg = max(maxdeg, __shfl_xor_sync(0xFFFFFFFFu, maxdeg, off));

    for (int i = 0; i < maxdeg; i += 4) {
        int4 sa = make_int4(0, 0, 0, 0);
        if (act && i < deg) sa = __ldg((const int4*)(sb + i));
        if (act && i + 0 < deg) {
            float ds = rsqrtf((float)(g_cnt[sa.x] + 1));
            float4 t = __ldg(&xp4[(size_t)sa.x * RS4 + c]);
            acc.x = fmaf(ds, t.x, acc.x); acc.y = fmaf(ds, t.y, acc.y);
            acc.z = fmaf(ds, t.z, acc.z); acc.w = fmaf(ds, t.w, acc.w);
        }
        if (act && i + 1 < deg) {
            float ds = rsqrtf((float)(g_cnt[sa.y] + 1));
            float4 t = __ldg(&xp4[(size_t)sa.y * RS4 + c]);
            acc.x = fmaf(ds, t.x, acc.x); acc.y = fmaf(ds, t.y, acc.y);
            acc.z = fmaf(ds, t.z, acc.z); acc.w = fmaf(ds, t.w, acc.w);
        }
        if (act && i + 2 < deg) {
            float ds = rsqrtf((float)(g_cnt[sa.z] + 1));
            float4 t = __ldg(&xp4[(size_t)sa.z * RS4 + c]);
            acc.x = fmaf(ds, t.x, acc.x); acc.y = fmaf(ds, t.y, acc.y);
            acc.z = fmaf(ds, t.z, acc.z); acc.w = fmaf(ds, t.w, acc.w);
        }
        if (act && i + 3 < deg) {
            float ds = rsqrtf((float)(g_cnt[sa.w] + 1));
            float4 t = __ldg(&xp4[(size_t)sa.w * RS4 + c]);
            acc.x = fmaf(ds, t.x, acc.x); acc.y = fmaf(ds, t.y, acc.y);
            acc.z = fmaf(ds, t.z, acc.z); acc.w = fmaf(ds, t.w, acc.w);
        }
    }
    if (act) {
        float sc = dv * dv;
        ((float4*)g_h1s)[(size_t)v * RS4 + c] =
            make_float4(sc * acc.x, sc * acc.y, sc * acc.z, sc * acc.w);
    }
}

// ---------------------------------------------------------------------------
// hop 2: 2 clusters per warp (16-lane halves, 10 active lanes each).
// yc = dinv_r * ( h1s[r] + sum_in h1s[s] ) + b ;  ycn = log_softmax(yc).
__global__ void hop2_kernel(const int* __restrict__ rep_idx,
                            const float* __restrict__ b) {
    int gwarp = (blockIdx.x * blockDim.x + threadIdx.x) >> 5;
    int lane  = threadIdx.x & 31;
    int h  = lane >> 4;           // half 0/1
    int l16 = lane & 15;
    int c = l16;                  // chunk 0..9 when active
    int j = gwarp * 2 + h;
    bool act = (l16 < 10) && (j < CC);

    const float4* h1s4 = (const float4*)g_h1s;
    float4 acc = make_float4(0.f, 0.f, 0.f, 0.f);
    float dv = 0.f;
    int deg = 0;
    const int* sb = g_srcbuf;
    int v = 0;
    if (j < CC) v = __ldg(&rep_idx[j]);
    if (act) {
        int cv = g_cnt[v];
        deg = min(cv, CAP);
        dv = rsqrtf((float)(cv + 1));
        acc = __ldg(&h1s4[(size_t)v * RS4 + c]);
        sb = g_srcbuf + v * CAP;
    }
    int maxdeg = deg;
    #pragma unroll
    for (int off = 16; off > 0; off >>= 1)
        maxdeg = max(maxdeg, __shfl_xor_sync(0xFFFFFFFFu, maxdeg, off));

    for (int i = 0; i < maxdeg; i += 4) {
        int4 sa = make_int4(0, 0, 0, 0);
        if (act && i < deg) sa = __ldg((const int4*)(sb + i));
        if (act && i + 0 < deg) {
            float4 t = __ldg(&h1s4[(size_t)sa.x * RS4 + c]);
            acc.x += t.x; acc.y += t.y; acc.z += t.z; acc.w += t.w;
        }
        if (act && i + 1 < deg) {
            float4 t = __ldg(&h1s4[(size_t)sa.y * RS4 + c]);
            acc.x += t.x; acc.y += t.y; acc.z += t.z; acc.w += t.w;
        }
        if (act && i + 2 < deg) {
            float4 t = __ldg(&h1s4[(size_t)sa.z * RS4 + c]);
            acc.x += t.x; acc.y += t.y; acc.z += t.z; acc.w += t.w;
        }
        if (act && i + 3 < deg) {
            float4 t = __ldg(&h1s4[(size_t)sa.w * RS4 + c]);
            acc.x += t.x; acc.y += t.y; acc.z += t.z; acc.w += t.w;
        }
    }

    float4 bb = make_float4(0.f, 0.f, 0.f, 0.f);
    if (act) bb = __ldg(&((const float4*)b)[c]);
    float4 val;
    val.x = dv * acc.x + bb.x;
    val.y = dv * acc.y + bb.y;
    val.z = dv * acc.z + bb.z;
    val.w = dv * acc.w + bb.w;

    // log_softmax over 40 values within each 16-lane half
    float m = act ? fmaxf(fmaxf(val.x, val.y), fmaxf(val.z, val.w)) : -INFINITY;
    #pragma unroll
    for (int off = 8; off > 0; off >>= 1)
        m = fmaxf(m, __shfl_xor_sync(0xFFFFFFFFu, m, off));
    float e = act ? (expf(val.x - m) + expf(val.y - m) +
                     expf(val.z - m) + expf(val.w - m)) : 0.0f;
    #pragma unroll
    for (int off = 8; off > 0; off >>= 1)
        e += __shfl_xor_sync(0xFFFFFFFFu, e, off);
    float lse = m + logf(e);

    if (act) {
        ((float4*)g_ycn)[(size_t)j * (OUTF / 4) + c] =
            make_float4(val.x - lse, val.y - lse, val.z - lse, val.w - lse);
    }
}

// ---------------------------------------------------------------------------
// out[i] = ycn[cluster_index[i]]   (pure float4 gather-copy)
__global__ void gather_out_kernel(const int* __restrict__ cluster_index,
                                  float4* __restrict__ out4) {
    int t = blockIdx.x * blockDim.x + threadIdx.x;
    const int TOT = NN * (OUTF / 4);               // 500000 float4s
    if (t >= TOT) return;
    int node = t / (OUTF / 4);
    int j    = t - node * (OUTF / 4);
    int cl = __ldg(&cluster_index[node]);
    out4[t] = __ldg(((const float4*)g_ycn) + (size_t)cl * (OUTF / 4) + j);
}

// ---------------------------------------------------------------------------
extern "C" void kernel_launch(void* const* d_in, const int* in_sizes, int n_in,
                              void* d_out, int out_size) {
    const float* x             = (const float*)d_in[0];
    const int*   edge_index    = (const int*)d_in[1];
    const int*   cluster_index = (const int*)d_in[2];
    const int*   rep_idx       = (const int*)d_in[3];
    const float* W             = (const float*)d_in[4];
    const float* b             = (const float*)d_in[5];
    float4*      out4          = (float4*)d_out;

    // zero the degree counters
    void* cntp = nullptr;
    cudaGetSymbolAddress(&cntp, g_cnt);
    cudaMemsetAsync(cntp, 0, NN * sizeof(int), 0);

    // fill (edge binning) and proj (x@W^T) run concurrently in one kernel
    fused_fill_proj_kernel<<<FUSEDB, 256>>>(edge_index, x, W);

    // propagation (dinv computed on the fly from counts)
    {
        int warps = (NN + 2) / 3;                          // 3 nodes per warp
        hop1_kernel<<<(warps * 32 + 255) / 256, 256>>>();
    }
    {
        int warps = (CC + 1) / 2;                          // 2 clusters per warp
        hop2_kernel<<<(warps * 32 + 255) / 256, 256>>>(rep_idx, b);
    }

    // scatter normalized logits
    gather_out_kernel<<<(NN * (OUTF / 4) + 255) / 256, 256>>>(cluster_index, out4);
}

// round 7
// speedup vs baseline: 1.0844x; 1.0844x over previous
#include <cuda_runtime.h>
#include <math.h>

#define NN   50000
#define EE   800000
#define CC   5000
#define DD   128
#define OUTF 40
#define CAP  64          // per-node in-edge bin capacity (max in-deg ~38)
#define CAPC 64          // per-cluster node bin capacity (max cluster size ~28)
#define RS   64          // padded feature row stride (floats) -> 256B aligned
#define RS4  16          // row stride in float4

// ---- scratch (device globals; no allocation allowed) ----
__device__ int   g_cnt[NN + CC];       // [0,NN): in-degree; [NN,NN+CC): cluster size
__device__ int   g_srcbuf[NN * CAP];   // binned in-edge source lists
__device__ int   g_clbuf[CC * CAPC];   // binned member-node lists per cluster
__device__ float g_dinv[NN];           // D^{-1/2}
__device__ float g_xps[NN * RS];       // dinv[v] * (x[v] @ W^T), padded rows
__device__ float g_h1s[NN * RS];       // dinv[v] * h1[v], padded rows

// ---- f32x2 packed helpers (Blackwell FFMA2) ----
__device__ __forceinline__ unsigned long long pk2(float lo, float hi) {
    unsigned long long r;
    asm("mov.b64 %0, {%1, %2};" : "=l"(r) : "f"(lo), "f"(hi));
    return r;
}
__device__ __forceinline__ unsigned long long fma2(unsigned long long a,
                                                   unsigned long long b,
                                                   unsigned long long c) {
    unsigned long long d;
    asm("fma.rn.f32x2 %0, %1, %2, %3;" : "=l"(d) : "l"(a), "l"(b), "l"(c));
    return d;
}
__device__ __forceinline__ void upk2(unsigned long long v, float& a, float& b) {
    asm("mov.b64 {%0, %1}, %2;" : "=f"(a), "=f"(b) : "l"(v));
}
__device__ __forceinline__ void acc4(float4& a, const float4& t) {
    a.x += t.x; a.y += t.y; a.z += t.z; a.w += t.w;
}

// ---------------------------------------------------------------------------
// fill: bin edges by dst (count+place) AND bin nodes by cluster, one kernel.
// Threads [0, EE/4): 4 edges each. Threads [EE/4, EE/4+NN/4): 4 nodes each.
__global__ void fill_kernel(const int* __restrict__ ei,
                            const int* __restrict__ cluster_index) {
    int t = blockIdx.x * blockDim.x + threadIdx.x;
    if (t < EE / 4) {
        int4 s = __ldg(((const int4*)ei) + t);
        int4 d = __ldg(((const int4*)(ei + EE)) + t);
        int p0 = atomicAdd(&g_cnt[d.x], 1);
        if (p0 < CAP) g_srcbuf[d.x * CAP + p0] = s.x;
        int p1 = atomicAdd(&g_cnt[d.y], 1);
        if (p1 < CAP) g_srcbuf[d.y * CAP + p1] = s.y;
        int p2 = atomicAdd(&g_cnt[d.z], 1);
        if (p2 < CAP) g_srcbuf[d.z * CAP + p2] = s.z;
        int p3 = atomicAdd(&g_cnt[d.w], 1);
        if (p3 < CAP) g_srcbuf[d.w * CAP + p3] = s.w;
    } else if (t < EE / 4 + NN / 4) {
        int q = t - EE / 4;
        int4 cl = __ldg(((const int4*)cluster_index) + q);
        int node = q * 4;
        int p0 = atomicAdd(&g_cnt[NN + cl.x], 1);
        if (p0 < CAPC) g_clbuf[cl.x * CAPC + p0] = node;
        int p1 = atomicAdd(&g_cnt[NN + cl.y], 1);
        if (p1 < CAPC) g_clbuf[cl.y * CAPC + p1] = node + 1;
        int p2 = atomicAdd(&g_cnt[NN + cl.z], 1);
        if (p2 < CAPC) g_clbuf[cl.z * CAPC + p2] = node + 2;
        int p3 = atomicAdd(&g_cnt[NN + cl.w], 1);
        if (p3 < CAPC) g_clbuf[cl.w * CAPC + p3] = node + 3;
    }
}

// ---------------------------------------------------------------------------
// xps[v] = dinv[v] * (x[v] @ W^T); dinv from in-degree counts (fill done).
__global__ void proj_kernel(const float* __restrict__ x,
                            const float* __restrict__ W) {
    __shared__ ulonglong2 Ws2[OUTF / 2][DD / 2];   // 20KB
    for (int t = threadIdx.x; t < (OUTF / 2) * (DD / 2); t += blockDim.x) {
        int o2 = t / (DD / 2);
        int d2 = t % (DD / 2);
        int d  = 2 * d2;
        float w00 = W[(2 * o2)     * DD + d    ];
        float w10 = W[(2 * o2 + 1) * DD + d    ];
        float w01 = W[(2 * o2)     * DD + d + 1];
        float w11 = W[(2 * o2 + 1) * DD + d + 1];
        Ws2[o2][d2] = make_ulonglong2(pk2(w00, w10), pk2(w01, w11));
    }
    __syncthreads();

    int row = blockIdx.x * blockDim.x + threadIdx.x;
    if (row >= NN) return;

    unsigned long long acc[OUTF / 2];
    #pragma unroll
    for (int o2 = 0; o2 < OUTF / 2; o2++) acc[o2] = 0ull;

    const float4* xr4 = (const float4*)(x + (size_t)row * DD);
    #pragma unroll 4
    for (int d4 = 0; d4 < DD / 4; d4++) {
        float4 xv = __ldg(&xr4[d4]);
        int d2 = d4 * 2;
        unsigned long long a0 = pk2(xv.x, xv.x);
        unsigned long long a1 = pk2(xv.y, xv.y);
        unsigned long long a2 = pk2(xv.z, xv.z);
        unsigned long long a3 = pk2(xv.w, xv.w);
        #pragma unroll
        for (int o2 = 0; o2 < OUTF / 2; o2++) {
            ulonglong2 w = Ws2[o2][d2];
            acc[o2] = fma2(a0, w.x, acc[o2]);
            acc[o2] = fma2(a1, w.y, acc[o2]);
        }
        #pragma unroll
        for (int o2 = 0; o2 < OUTF / 2; o2++) {
            ulonglong2 w = Ws2[o2][d2 + 1];
            acc[o2] = fma2(a2, w.x, acc[o2]);
            acc[o2] = fma2(a3, w.y, acc[o2]);
        }
    }

    float dv = rsqrtf((float)(g_cnt[row] + 1));   // +1 self loop
    g_dinv[row] = dv;
    float2* op2 = (float2*)(g_xps + (size_t)row * RS);
    #pragma unroll
    for (int o2 = 0; o2 < OUTF / 2; o2++) {
        float f0, f1;
        upk2(acc[o2], f0, f1);
        op2[o2] = make_float2(dv * f0, dv * f1);
    }
}

// ---------------------------------------------------------------------------
// Gather-sum core: acc = rows[v] + sum_in rows[s]; 4-wide edge unroll.
// One warp per node; lanes 0..9 each own a float4 chunk (40 floats).
__device__ __forceinline__ float4 gather_row_sum(const float4* __restrict__ rows4,
                                                 int v, int lane, bool act) {
    float4 acc = make_float4(0.f, 0.f, 0.f, 0.f);
    if (act) acc = __ldg(&rows4[(size_t)v * RS4 + lane]);
    int deg = g_cnt[v];
    if (deg > CAP) deg = CAP;
    const int* sb = g_srcbuf + v * CAP;
    int i = 0;
    for (; i + 4 <= deg; i += 4) {
        int4 sa = __ldg((const int4*)(sb + i));
        if (act) {
            float4 t0 = __ldg(&rows4[(size_t)sa.x * RS4 + lane]);
            float4 t1 = __ldg(&rows4[(size_t)sa.y * RS4 + lane]);
            float4 t2 = __ldg(&rows4[(size_t)sa.z * RS4 + lane]);
            float4 t3 = __ldg(&rows4[(size_t)sa.w * RS4 + lane]);
            acc4(acc, t0); acc4(acc, t1); acc4(acc, t2); acc4(acc, t3);
        }
    }
    for (; i < deg; i++) {
        int s = __ldg(&sb[i]);
        if (act) {
            float4 t = __ldg(&rows4[(size_t)s * RS4 + lane]);
            acc4(acc, t);
        }
    }
    return acc;
}

// hop 1 (all nodes): h1s[v] = dinv[v]^2 * ( xps[v] + sum_in xps[s] )
__global__ void hop1_kernel() {
    int warp = (blockIdx.x * blockDim.x + threadIdx.x) >> 5;
    int lane = threadIdx.x & 31;
    if (warp >= NN) return;
    int v = warp;
    const bool act = (lane < 10);
    float4 acc = gather_row_sum((const float4*)g_xps, v, lane, act);
    float dv = g_dinv[v];
    float sc = dv * dv;
    if (act) {
        ((float4*)g_h1s)[(size_t)v * RS4 + lane] =
            make_float4(sc * acc.x, sc * acc.y, sc * acc.z, sc * acc.w);
    }
}

// hop 2 (rep rows) + bias + log_softmax + DIRECT scatter to member nodes.
__global__ void hop2_scatter_kernel(const int* __restrict__ rep_idx,
                                    const float* __restrict__ b,
                                    float4* __restrict__ out4) {
    int warp = (blockIdx.x * blockDim.x + threadIdx.x) >> 5;
    int lane = threadIdx.x & 31;
    if (warp >= CC) return;
    int j = warp;
    int v = __ldg(&rep_idx[j]);
    const bool act = (lane < 10);
    float4 acc = gather_row_sum((const float4*)g_h1s, v, lane, act);

    float dv = g_dinv[v];
    float4 bb = make_float4(0.f, 0.f, 0.f, 0.f);
    if (act) bb = __ldg(&((const float4*)b)[lane]);
    float4 val;
    val.x = dv * acc.x + bb.x;
    val.y = dv * acc.y + bb.y;
    val.z = dv * acc.z + bb.z;
    val.w = dv * acc.w + bb.w;

    // warp-level log_softmax over the 40 values held by lanes 0..9
    float m = act ? fmaxf(fmaxf(val.x, val.y), fmaxf(val.z, val.w)) : -INFINITY;
    #pragma unroll
    for (int off = 16; off > 0; off >>= 1)
        m = fmaxf(m, __shfl_xor_sync(0xFFFFFFFFu, m, off));
    float e = act ? (expf(val.x - m) + expf(val.y - m) +
                     expf(val.z - m) + expf(val.w - m)) : 0.0f;
    #pragma unroll
    for (int off = 16; off > 0; off >>= 1)
        e += __shfl_xor_sync(0xFFFFFFFFu, e, off);
    float lse = m + logf(e);

    float4 res = make_float4(val.x - lse, val.y - lse, val.z - lse, val.w - lse);

    // scatter to every member node of this cluster (rows are 160B, float4-aligned)
    int nm = g_cnt[NN + j];
    if (nm > CAPC) nm = CAPC;
    const int* cb = g_clbuf + j * CAPC;
    for (int m2 = 0; m2 < nm; m2++) {
        int node = __ldg(&cb[m2]);              // broadcast across warp
        if (act) out4[(size_t)node * (OUTF / 4) + lane] = res;
    }
}

// ---------------------------------------------------------------------------
extern "C" void kernel_launch(void* const* d_in, const int* in_sizes, int n_in,
                              void* d_out, int out_size) {
    const float* x             = (const float*)d_in[0];
    const int*   edge_index    = (const int*)d_in[1];
    const int*   cluster_index = (const int*)d_in[2];
    const int*   rep_idx       = (const int*)d_in[3];
    const float* W             = (const float*)d_in[4];
    const float* b             = (const float*)d_in[5];
    float4*      out4          = (float4*)d_out;

    // zero both counter arrays in one memset
    void* cntp = nullptr;
    cudaGetSymbolAddress(&cntp, g_cnt);
    cudaMemsetAsync(cntp, 0, (NN + CC) * sizeof(int), 0);

    // bin edges by dst + bin nodes by cluster (one kernel)
    {
        int threads = EE / 4 + NN / 4;
        fill_kernel<<<(threads + 255) / 256, 256>>>(edge_index, cluster_index);
    }

    // project then propagate (SGC: A^2 (x W^T) == (A^2 x) W^T), scales folded in
    proj_kernel<<<(NN + 255) / 256, 256>>>(x, W);
    hop1_kernel<<<(NN * 32 + 255) / 256, 256>>>();
    hop2_scatter_kernel<<<(CC * 32 + 255) / 256, 256>>>(rep_idx, b, out4);
}

// round 8
// speedup vs baseline: 1.1338x; 1.0456x over previous
#include <cuda_runtime.h>
#include <math.h>

#define NN   50000
#define EE   800000
#define CC   5000
#define DD   128
#define OUTF 40
#define CAP  64          // per-node in-edge bin capacity (max in-deg ~38)
#define CAPC 64          // per-cluster node bin capacity
#define RS   64          // padded feature row stride (floats) -> 256B aligned
#define RS4  16          // row stride in float4
#define FULLM 0xFFFFFFFFu

// ---- scratch (device globals; no allocation allowed) ----
__device__ int   g_cnt[NN + CC];       // [0,NN): in-degree; [NN,NN+CC): cluster size
__device__ int   g_srcbuf[NN * CAP];   // binned in-edge source lists
__device__ int   g_clbuf[CC * CAPC];   // binned member-node lists per cluster
__device__ float g_dinv[NN];           // D^{-1/2}
__device__ float g_xps[NN * RS];       // dinv[v] * (x[v] @ W^T), padded rows
__device__ float g_h1s[NN * RS];       // dinv[v] * h1[v], padded rows

// ---- f32x2 packed helpers (Blackwell FFMA2) ----
__device__ __forceinline__ unsigned long long pk2(float lo, float hi) {
    unsigned long long r;
    asm("mov.b64 %0, {%1, %2};" : "=l"(r) : "f"(lo), "f"(hi));
    return r;
}
__device__ __forceinline__ unsigned long long fma2(unsigned long long a,
                                                   unsigned long long b,
                                                   unsigned long long c) {
    unsigned long long d;
    asm("fma.rn.f32x2 %0, %1, %2, %3;" : "=l"(d) : "l"(a), "l"(b), "l"(c));
    return d;
}
__device__ __forceinline__ void upk2(unsigned long long v, float& a, float& b) {
    asm("mov.b64 {%0, %1}, %2;" : "=f"(a), "=f"(b) : "l"(v));
}
__device__ __forceinline__ void acc4(float4& a, const float4& t) {
    a.x += t.x; a.y += t.y; a.z += t.z; a.w += t.w;
}

// ---------------------------------------------------------------------------
// fill: bin edges by dst (count+place) AND bin nodes by cluster, one kernel.
__global__ void fill_kernel(const int* __restrict__ ei,
                            const int* __restrict__ cluster_index) {
    int t = blockIdx.x * blockDim.x + threadIdx.x;
    if (t < EE / 4) {
        int4 s = __ldg(((const int4*)ei) + t);
        int4 d = __ldg(((const int4*)(ei + EE)) + t);
        int p0 = atomicAdd(&g_cnt[d.x], 1);
        if (p0 < CAP) g_srcbuf[d.x * CAP + p0] = s.x;
        int p1 = atomicAdd(&g_cnt[d.y], 1);
        if (p1 < CAP) g_srcbuf[d.y * CAP + p1] = s.y;
        int p2 = atomicAdd(&g_cnt[d.z], 1);
        if (p2 < CAP) g_srcbuf[d.z * CAP + p2] = s.z;
        int p3 = atomicAdd(&g_cnt[d.w], 1);
        if (p3 < CAP) g_srcbuf[d.w * CAP + p3] = s.w;
    } else if (t < EE / 4 + NN / 4) {
        int q = t - EE / 4;
        int4 cl = __ldg(((const int4*)cluster_index) + q);
        int node = q * 4;
        int p0 = atomicAdd(&g_cnt[NN + cl.x], 1);
        if (p0 < CAPC) g_clbuf[cl.x * CAPC + p0] = node;
        int p1 = atomicAdd(&g_cnt[NN + cl.y], 1);
        if (p1 < CAPC) g_clbuf[cl.y * CAPC + p1] = node + 1;
        int p2 = atomicAdd(&g_cnt[NN + cl.z], 1);
        if (p2 < CAPC) g_clbuf[cl.z * CAPC + p2] = node + 2;
        int p3 = atomicAdd(&g_cnt[NN + cl.w], 1);
        if (p3 < CAPC) g_clbuf[cl.w * CAPC + p3] = node + 3;
    }
}

// ---------------------------------------------------------------------------
// xps[v] = dinv[v] * (x[v] @ W^T); dinv from in-degree counts (fill done).
__global__ void proj_kernel(const float* __restrict__ x,
                            const float* __restrict__ W) {
    __shared__ ulonglong2 Ws2[OUTF / 2][DD / 2];   // 20KB
    for (int t = threadIdx.x; t < (OUTF / 2) * (DD / 2); t += blockDim.x) {
        int o2 = t / (DD / 2);
        int d2 = t % (DD / 2);
        int d  = 2 * d2;
        float w00 = W[(2 * o2)     * DD + d    ];
        float w10 = W[(2 * o2 + 1) * DD + d    ];
        float w01 = W[(2 * o2)     * DD + d + 1];
        float w11 = W[(2 * o2 + 1) * DD + d + 1];
        Ws2[o2][d2] = make_ulonglong2(pk2(w00, w10), pk2(w01, w11));
    }
    __syncthreads();

    int row = blockIdx.x * blockDim.x + threadIdx.x;
    if (row >= NN) return;

    unsigned long long acc[OUTF / 2];
    #pragma unroll
    for (int o2 = 0; o2 < OUTF / 2; o2++) acc[o2] = 0ull;

    const float4* xr4 = (const float4*)(x + (size_t)row * DD);
    #pragma unroll 4
    for (int d4 = 0; d4 < DD / 4; d4++) {
        float4 xv = __ldg(&xr4[d4]);
        int d2 = d4 * 2;
        unsigned long long a0 = pk2(xv.x, xv.x);
        unsigned long long a1 = pk2(xv.y, xv.y);
        unsigned long long a2 = pk2(xv.z, xv.z);
        unsigned long long a3 = pk2(xv.w, xv.w);
        #pragma unroll
        for (int o2 = 0; o2 < OUTF / 2; o2++) {
            ulonglong2 w = Ws2[o2][d2];
            acc[o2] = fma2(a0, w.x, acc[o2]);
            acc[o2] = fma2(a1, w.y, acc[o2]);
        }
        #pragma unroll
        for (int o2 = 0; o2 < OUTF / 2; o2++) {
            ulonglong2 w = Ws2[o2][d2 + 1];
            acc[o2] = fma2(a2, w.x, acc[o2]);
            acc[o2] = fma2(a3, w.y, acc[o2]);
        }
    }

    float dv = rsqrtf((float)(g_cnt[row] + 1));   // +1 self loop
    g_dinv[row] = dv;
    float2* op2 = (float2*)(g_xps + (size_t)row * RS);
    #pragma unroll
    for (int o2 = 0; o2 < OUTF / 2; o2++) {
        float f0, f1;
        upk2(acc[o2], f0, f1);
        op2[o2] = make_float2(dv * f0, dv * f1);
    }
}

// ---------------------------------------------------------------------------
// Gather-sum v2: lane-parallel index load + shuffle broadcast.
// One coalesced LDG fetches up to 32 edge indices; then ALL row loads are
// independent (no per-iteration index dependency). deg is warp-uniform.
__device__ __forceinline__ float4 gather_row_sum(const float4* __restrict__ rows4,
                                                 int v, int lane, bool act) {
    int deg = g_cnt[v];
    if (deg > CAP) deg = CAP;
    const int* sb = g_srcbuf + v * CAP;
    int myidx = (lane < deg) ? __ldg(&sb[lane]) : 0;   // one coalesced load

    float4 acc = make_float4(0.f, 0.f, 0.f, 0.f);
    if (act) acc = __ldg(&rows4[(size_t)v * RS4 + lane]);

    int lim = deg < 32 ? deg : 32;
    int e = 0;
    for (; e + 4 <= lim; e += 4) {
        int s0 = __shfl_sync(FULLM, myidx, e + 0);
        int s1 = __shfl_sync(FULLM, myidx, e + 1);
        int s2 = __shfl_sync(FULLM, myidx, e + 2);
        int s3 = __shfl_sync(FULLM, myidx, e + 3);
        if (act) {
            float4 t0 = __ldg(&rows4[(size_t)s0 * RS4 + lane]);
            float4 t1 = __ldg(&rows4[(size_t)s1 * RS4 + lane]);
            float4 t2 = __ldg(&rows4[(size_t)s2 * RS4 + lane]);
            float4 t3 = __ldg(&rows4[(size_t)s3 * RS4 + lane]);
            acc4(acc, t0); acc4(acc, t1); acc4(acc, t2); acc4(acc, t3);
        }
    }
    for (; e < lim; e++) {
        int s = __shfl_sync(FULLM, myidx, e);
        if (act) {
            float4 t = __ldg(&rows4[(size_t)s * RS4 + lane]);
            acc4(acc, t);
        }
    }
    // rare tail: deg > 32 (Poisson(16) upper tail, a handful of nodes)
    for (; e < deg; e++) {
        int s = __ldg(&sb[e]);
        if (act) {
            float4 t = __ldg(&rows4[(size_t)s * RS4 + lane]);
            acc4(acc, t);
        }
    }
    return acc;
}

// hop 1 (all nodes): h1s[v] = dinv[v]^2 * ( xps[v] + sum_in xps[s] )
__global__ void hop1_kernel() {
    int warp = (blockIdx.x * blockDim.x + threadIdx.x) >> 5;
    int lane = threadIdx.x & 31;
    if (warp >= NN) return;
    int v = warp;
    const bool act = (lane < 10);
    float4 acc = gather_row_sum((const float4*)g_xps, v, lane, act);
    float dv = g_dinv[v];
    float sc = dv * dv;
    if (act) {
        ((float4*)g_h1s)[(size_t)v * RS4 + lane] =
            make_float4(sc * acc.x, sc * acc.y, sc * acc.z, sc * acc.w);
    }
}

// hop 2 (rep rows) + bias + log_softmax + DIRECT scatter to member nodes.
__global__ void hop2_scatter_kernel(const int* __restrict__ rep_idx,
                                    const float* __restrict__ b,
                                    float4* __restrict__ out4) {
    int warp = (blockIdx.x * blockDim.x + threadIdx.x) >> 5;
    int lane = threadIdx.x & 31;
    if (warp >= CC) return;
    int j = warp;
    int v = __ldg(&rep_idx[j]);
    const bool act = (lane < 10);
    float4 acc = gather_row_sum((const float4*)g_h1s, v, lane, act);

    float dv = g_dinv[v];
    float4 bb = make_float4(0.f, 0.f, 0.f, 0.f);
    if (act) bb = __ldg(&((const float4*)b)[lane]);
    float4 val;
    val.x = dv * acc.x + bb.x;
    val.y = dv * acc.y + bb.y;
    val.z = dv * acc.z + bb.z;
    val.w = dv * acc.w + bb.w;

    // warp-level log_softmax over the 40 values held by lanes 0..9
    float m = act ? fmaxf(fmaxf(val.x, val.y), fmaxf(val.z, val.w)) : -INFINITY;
    #pragma unroll
    for (int off = 16; off > 0; off >>= 1)
        m = fmaxf(m, __shfl_xor_sync(FULLM, m, off));
    float e = act ? (expf(val.x - m) + expf(val.y - m) +
                     expf(val.z - m) + expf(val.w - m)) : 0.0f;
    #pragma unroll
    for (int off = 16; off > 0; off >>= 1)
        e += __shfl_xor_sync(FULLM, e, off);
    float lse = m + logf(e);

    float4 res = make_float4(val.x - lse, val.y - lse, val.z - lse, val.w - lse);

    // scatter to every member node of this cluster (rows are 160B, f4-aligned)
    int nm = g_cnt[NN + j];
    if (nm > CAPC) nm = CAPC;
    const int* cb = g_clbuf + j * CAPC;
    for (int m2 = 0; m2 < nm; m2++) {
        int node = __ldg(&cb[m2]);              // broadcast across warp
        if (act) out4[(size_t)node * (OUTF / 4) + lane] = res;
    }
}

// ---------------------------------------------------------------------------
extern "C" void kernel_launch(void* const* d_in, const int* in_sizes, int n_in,
                              void* d_out, int out_size) {
    const float* x             = (const float*)d_in[0];
    const int*   edge_index    = (const int*)d_in[1];
    const int*   cluster_index = (const int*)d_in[2];
    const int*   rep_idx       = (const int*)d_in[3];
    const float* W             = (const float*)d_in[4];
    const float* b             = (const float*)d_in[5];
    float4*      out4          = (float4*)d_out;

    // zero both counter arrays in one memset
    void* cntp = nullptr;
    cudaGetSymbolAddress(&cntp, g_cnt);
    cudaMemsetAsync(cntp, 0, (NN + CC) * sizeof(int), 0);

    // bin edges by dst + bin nodes by cluster (one kernel)
    {
        int threads = EE / 4 + NN / 4;
        fill_kernel<<<(threads + 255) / 256, 256>>>(edge_index, cluster_index);
    }

    // project then propagate (SGC: A^2 (x W^T) == (A^2 x) W^T), scales folded in
    proj_kernel<<<(NN + 255) / 256, 256>>>(x, W);
    hop1_kernel<<<(NN * 32 + 255) / 256, 256>>>();
    hop2_scatter_kernel<<<(CC * 32 + 255) / 256, 256>>>(rep_idx, b, out4);
}